// round 12
// baseline (speedup 1.0000x reference)
#include <cuda_runtime.h>

// ts_cov: sliding-window pairwise covariance.
// x: [B=256, T=512, F=32] f32 -> out: [B, S=508, C=496] f32
// cov[b,s,c(i,j)] = mean5(x_i x_j) - mean5(x_i)*mean5(x_j)
//
// Thread t owns ADJACENT pairs c = 2t, 2t+1, advanced together with packed
// f32x2 arithmetic; one STG.64 (evict-first) per window. Uniform tiles
// (last tile clamped; overlap recomputed bit-identically). Each block now
// processes 4 consecutive batches at one s0, double-buffering the next
// batch's x tile via cp.async while computing the current one, so stores
// stream continuously and block prologues are hidden.

#define B_DIM 256
#define T_DIM 512
#define F_DIM 32
#define W 5
#define S_DIM (T_DIM - W + 1)            // 508
#define C_DIM (F_DIM * (F_DIM - 1) / 2)  // 496
#define HALF_C (C_DIM / 2)               // 248
#define S_TILE 64
#define ROWS (S_TILE + W - 1)            // 68
#define NTHREADS 256
#define TILES_PER_B ((S_DIM + S_TILE - 1) / S_TILE) // 8
#define B_PER_BLK 4
#define B_CHUNKS (B_DIM / B_PER_BLK)     // 64
#define TILE_V16 (ROWS * F_DIM / 4)      // 544 16-byte chunks

typedef unsigned long long u64;

__device__ __forceinline__ u64 pack2(float lo, float hi) {
    u64 r;
    asm("mov.b64 %0, {%1, %2};" : "=l"(r) : "r"(__float_as_uint(lo)), "r"(__float_as_uint(hi)));
    return r;
}
__device__ __forceinline__ float2 as_f2(u64 v) {
    float2 f;
    unsigned a, b;
    asm("mov.b64 {%0, %1}, %2;" : "=r"(a), "=r"(b) : "l"(v));
    f.x = __uint_as_float(a); f.y = __uint_as_float(b);
    return f;
}
__device__ __forceinline__ u64 mul2(u64 a, u64 b) {
    u64 r; asm("mul.rn.f32x2 %0, %1, %2;" : "=l"(r) : "l"(a), "l"(b)); return r;
}
__device__ __forceinline__ u64 add2(u64 a, u64 b) {
    u64 r; asm("add.rn.f32x2 %0, %1, %2;" : "=l"(r) : "l"(a), "l"(b)); return r;
}
__device__ __forceinline__ u64 sub2(u64 a, u64 b) {
    u64 r; asm("sub.rn.f32x2 %0, %1, %2;" : "=l"(r) : "l"(a), "l"(b)); return r;
}
__device__ __forceinline__ u64 fma2(u64 a, u64 b, u64 c) {
    u64 r; asm("fma.rn.f32x2 %0, %1, %2, %3;" : "=l"(r) : "l"(a), "l"(b), "l"(c)); return r;
}

// closed-form pair decode c -> (i, j), triu_indices(F, k=1) order
__device__ __forceinline__ void decode_pair(int c, int& io, int& jo) {
    const int TF = 2 * F_DIM - 1; // 63
    float disc = (float)(TF * TF - 8 * c);
    int i = (int)(((float)TF - sqrtf(disc)) * 0.5f);
    int off = (i * (TF - i)) >> 1;
    if (c < off)                          { --i; off = (i * (TF - i)) >> 1; }
    else if (c >= off + (F_DIM - 1 - i))  { ++i; off = (i * (TF - i)) >> 1; }
    io = i; jo = c - off + i + 1;
}

// async 16B copies of one x tile into a smem buffer (issued, not waited)
__device__ __forceinline__ void prefetch_tile(float (*dst)[F_DIM],
                                              const float* __restrict__ gsrc,
                                              int tid) {
    unsigned sbase = (unsigned)__cvta_generic_to_shared(&dst[0][0]);
    #pragma unroll 1
    for (int idx = tid; idx < TILE_V16; idx += NTHREADS) {
        asm volatile("cp.async.cg.shared.global [%0], [%1], 16;\n"
                     :: "r"(sbase + idx * 16), "l"(gsrc + idx * 4));
    }
    asm volatile("cp.async.commit_group;\n");
}

__global__ __launch_bounds__(NTHREADS, 5)
void ts_cov_kernel(const float* __restrict__ x, float* __restrict__ out) {
    __shared__ float sx[2][ROWS][F_DIM];

    const int b0  = blockIdx.y * B_PER_BLK;
    const int s0  = min(blockIdx.x * S_TILE, S_DIM - S_TILE); // uniform tiles
    const int tid = threadIdx.x;

    // kick off first tile
    prefetch_tile(sx[0], x + ((long)b0 * T_DIM + s0) * F_DIM, tid);

    // per-thread pair decode (constant across batches)
    int iA, jA, iB, jB;
    decode_pair(2 * tid,     iA, jA);
    decode_pair(2 * tid + 1, iB, jB);
    const bool active = (tid < HALF_C);

    const u64 INVP = pack2(0.2f, 0.2f);     //  1/W
    const u64 NI25 = pack2(-0.04f, -0.04f); // -1/W^2

    #pragma unroll 1
    for (int bb = 0; bb < B_PER_BLK; ++bb) {
        // wait for buffer bb&1; barrier also retires all reads of the other buffer
        asm volatile("cp.async.wait_group 0;\n");
        __syncthreads();

        if (bb + 1 < B_PER_BLK)
            prefetch_tile(sx[(bb + 1) & 1],
                          x + ((long)(b0 + bb + 1) * T_DIM + s0) * F_DIM, tid);

        if (active) {
            const float (*sxb)[F_DIM] = sx[bb & 1];

            // init sliding rings (values; exit products recomputed bit-identically)
            u64 xr[W], yr[W];
            u64 s2x = 0ull, s2y = 0ull, s2p = 0ull;
            #pragma unroll
            for (int t = 0; t < W; ++t) {
                const u64 x2 = pack2(sxb[t][iA], sxb[t][iB]);
                const u64 y2 = pack2(sxb[t][jA], sxb[t][jB]);
                const u64 p2 = mul2(x2, y2);
                xr[t] = x2; yr[t] = y2;
                s2x = add2(s2x, x2); s2y = add2(s2y, y2); s2p = add2(s2p, p2);
            }

            float* o = out + ((long)(b0 + bb) * S_DIM + s0) * C_DIM + 2 * tid;

            #pragma unroll
            for (int sl = 0; sl < S_TILE; ++sl) {
                const u64 cov2 = fma2(mul2(s2x, s2y), NI25, mul2(s2p, INVP));
                __stcs((float2*)(o + (long)sl * C_DIM), as_f2(cov2));
                if (sl + 1 < S_TILE) {
                    const int r = sl + W, k = sl % W;
                    const u64 x2 = pack2(sxb[r][iA], sxb[r][iB]);
                    const u64 y2 = pack2(sxb[r][jA], sxb[r][jB]);
                    const u64 po = mul2(xr[k], yr[k]);
                    const u64 p2 = mul2(x2, y2);
                    s2p = add2(s2p, sub2(p2, po));
                    s2x = add2(s2x, sub2(x2, xr[k]));
                    s2y = add2(s2y, sub2(y2, yr[k]));
                    xr[k] = x2; yr[k] = y2;
                }
            }
        }
        __syncthreads();   // all reads of buffer bb&1 done before it is refilled
    }
}

extern "C" void kernel_launch(void* const* d_in, const int* in_sizes, int n_in,
                              void* d_out, int out_size) {
    const float* x = (const float*)d_in[0];
    float* out = (float*)d_out;
    (void)in_sizes; (void)n_in; (void)out_size;
    dim3 grid(TILES_PER_B, B_CHUNKS);
    ts_cov_kernel<<<grid, NTHREADS>>>(x, out);
}

// round 14
// speedup vs baseline: 1.2650x; 1.2650x over previous
#include <cuda_runtime.h>

// ts_cov: sliding-window pairwise covariance.
// x: [B=256, T=512, F=32] f32 -> out: [B, S=508, C=496] f32
// cov[b,s,c(i,j)] = mean5(x_i x_j) - mean5(x_i)*mean5(x_j)
//
// Thread t owns ADJACENT pairs c = 2t, 2t+1, advanced together with packed
// f32x2 arithmetic; one STG.64 (evict-first) per window, immediate offsets
// off a 64-bit base. Grid 8x256 (2048 blocks, 5 blocks/SM). Exact-write
// tails (templates <64>/<60>, no duplicate stores). Tile staged via
// cp.async (no LDG->reg->STS round-trip; load overlaps pair decode).

#define B_DIM 256
#define T_DIM 512
#define F_DIM 32
#define W 5
#define S_DIM (T_DIM - W + 1)            // 508
#define C_DIM (F_DIM * (F_DIM - 1) / 2)  // 496
#define HALF_C (C_DIM / 2)               // 248
#define S_TILE 64
#define ROWS (S_TILE + W - 1)            // 68
#define NTHREADS 256
#define TILES_PER_B ((S_DIM + S_TILE - 1) / S_TILE) // 8
#define TAIL_CNT (S_DIM - (TILES_PER_B - 1) * S_TILE) // 60

typedef unsigned long long u64;

__device__ __forceinline__ u64 pack2(float lo, float hi) {
    u64 r;
    asm("mov.b64 %0, {%1, %2};" : "=l"(r) : "r"(__float_as_uint(lo)), "r"(__float_as_uint(hi)));
    return r;
}
__device__ __forceinline__ float2 as_f2(u64 v) {
    float2 f;
    unsigned a, b;
    asm("mov.b64 {%0, %1}, %2;" : "=r"(a), "=r"(b) : "l"(v));
    f.x = __uint_as_float(a); f.y = __uint_as_float(b);
    return f;
}
__device__ __forceinline__ u64 mul2(u64 a, u64 b) {
    u64 r; asm("mul.rn.f32x2 %0, %1, %2;" : "=l"(r) : "l"(a), "l"(b)); return r;
}
__device__ __forceinline__ u64 add2(u64 a, u64 b) {
    u64 r; asm("add.rn.f32x2 %0, %1, %2;" : "=l"(r) : "l"(a), "l"(b)); return r;
}
__device__ __forceinline__ u64 sub2(u64 a, u64 b) {
    u64 r; asm("sub.rn.f32x2 %0, %1, %2;" : "=l"(r) : "l"(a), "l"(b)); return r;
}
__device__ __forceinline__ u64 fma2(u64 a, u64 b, u64 c) {
    u64 r; asm("fma.rn.f32x2 %0, %1, %2, %3;" : "=l"(r) : "l"(a), "l"(b), "l"(c)); return r;
}

// closed-form pair decode c -> (i, j), triu_indices(F, k=1) order
__device__ __forceinline__ void decode_pair(int c, int& io, int& jo) {
    const int TF = 2 * F_DIM - 1; // 63
    float disc = (float)(TF * TF - 8 * c);
    int i = (int)(((float)TF - sqrtf(disc)) * 0.5f);
    int off = (i * (TF - i)) >> 1;
    if (c < off)                          { --i; off = (i * (TF - i)) >> 1; }
    else if (c >= off + (F_DIM - 1 - i))  { ++i; off = (i * (TF - i)) >> 1; }
    io = i; jo = c - off + i + 1;
}

template <int SCNT>
__device__ __forceinline__ void cov_tile(const float (*sx)[F_DIM], float* o,
                                         int iA, int jA, int iB, int jB) {
    const u64 INVP = pack2(0.2f, 0.2f);     //  1/W
    const u64 NI25 = pack2(-0.04f, -0.04f); // -1/W^2

    // Init sliding rings (values; exit products recomputed, bit-identical)
    u64 xr[W], yr[W];
    u64 s2x = 0ull, s2y = 0ull, s2p = 0ull;
    #pragma unroll
    for (int t = 0; t < W; ++t) {
        const u64 x2 = pack2(sx[t][iA], sx[t][iB]);
        const u64 y2 = pack2(sx[t][jA], sx[t][jB]);
        const u64 p2 = mul2(x2, y2);
        xr[t] = x2; yr[t] = y2;
        s2x = add2(s2x, x2); s2y = add2(s2y, y2); s2p = add2(s2p, p2);
    }

    #pragma unroll
    for (int sl = 0; sl < SCNT; ++sl) {
        const u64 cov2 = fma2(mul2(s2x, s2y), NI25, mul2(s2p, INVP));
        __stcs((float2*)(o + (long)sl * C_DIM), as_f2(cov2));
        if (sl + 1 < SCNT) {
            const int r = sl + W, k = sl % W;
            const u64 x2 = pack2(sx[r][iA], sx[r][iB]);
            const u64 y2 = pack2(sx[r][jA], sx[r][jB]);
            const u64 po = mul2(xr[k], yr[k]);
            const u64 p2 = mul2(x2, y2);
            s2p = add2(s2p, sub2(p2, po));
            s2x = add2(s2x, sub2(x2, xr[k]));
            s2y = add2(s2y, sub2(y2, yr[k]));
            xr[k] = x2; yr[k] = y2;
        }
    }
}

__global__ __launch_bounds__(NTHREADS, 5)
void ts_cov_kernel(const float* __restrict__ x, float* __restrict__ out) {
    __shared__ float sx[ROWS][F_DIM];

    const int b     = blockIdx.y;
    const int s0    = blockIdx.x * S_TILE;
    const bool full = (s0 + S_TILE <= S_DIM);
    const int rows  = (full ? S_TILE : TAIL_CNT) + W - 1;
    const int tid   = threadIdx.x;

    // ---- Stage tile via cp.async (16B chunks), overlapping pair decode ----
    {
        const float* gsrc = x + ((long)b * T_DIM + s0) * F_DIM;
        unsigned sbase = (unsigned)__cvta_generic_to_shared(&sx[0][0]);
        const int nv16 = rows * (F_DIM / 4);
        #pragma unroll 1
        for (int idx = tid; idx < nv16; idx += NTHREADS) {
            asm volatile("cp.async.cg.shared.global [%0], [%1], 16;\n"
                         :: "r"(sbase + idx * 16), "l"(gsrc + idx * 4));
        }
        asm volatile("cp.async.commit_group;\n");
    }

    // pair decode overlaps the in-flight cp.async
    int iA, jA, iB, jB;
    decode_pair(2 * tid,     iA, jA);
    decode_pair(2 * tid + 1, iB, jB);

    asm volatile("cp.async.wait_group 0;\n");
    __syncthreads();

    if (tid >= HALF_C) return;

    // even element offset -> 8B-aligned float2 stores, immediate sl*C_DIM
    float* o = out + ((long)b * S_DIM + s0) * C_DIM + 2 * tid;

    if (full) cov_tile<S_TILE>(sx, o, iA, jA, iB, jB);
    else      cov_tile<TAIL_CNT>(sx, o, iA, jA, iB, jB);
}

extern "C" void kernel_launch(void* const* d_in, const int* in_sizes, int n_in,
                              void* d_out, int out_size) {
    const float* x = (const float*)d_in[0];
    float* out = (float*)d_out;
    (void)in_sizes; (void)n_in; (void)out_size;
    dim3 grid(TILES_PER_B, B_DIM);
    ts_cov_kernel<<<grid, NTHREADS>>>(x, out);
}